// round 4
// baseline (speedup 1.0000x reference)
#include <cuda_runtime.h>

// Depthwise separable FIR [1,3,3,1]x[1,3,3,1]/64, pad 1 on all sides,
// in:  [16,256,128,128] f32  -> out: [16,256,127,127] f32
//
// One block processes one (n,c) plane's 32-output-row band, full width.
// Two-pass separable in shared memory. Input loaded once as float4.

#define H_IN   128
#define W_IN   128
#define H_OUT  127
#define W_OUT  127
#define ROWS   32            // output rows per block
#define NROWS  (ROWS + 3)    // input rows needed (halo -1..+2)
#define SW     132           // smem input row width: cols -1..129 -> idx 0..130, pad to 132
#define NTHREADS 256

__global__ __launch_bounds__(NTHREADS)
void fir4x4_kernel(const float* __restrict__ x, float* __restrict__ out) {
    const int y0    = blockIdx.x * ROWS;     // output row tile start (0,32,64,96)
    const int plane = blockIdx.y;            // n*C + c, 0..4095

    __shared__ float sin_t[NROWS][SW];       // raw input tile (col offset +1)
    __shared__ float sh_t [NROWS][W_IN];     // horizontal-pass results

    const int tid = threadIdx.x;
    const float* xp = x + (size_t)plane * (H_IN * W_IN);

    // ---- load input tile: NROWS rows x 128 cols, vectorized float4 ----
    // smem col index = input col + 1. Cols 0 and 129..131 zeroed below.
    #pragma unroll
    for (int i = tid; i < NROWS * (W_IN / 4); i += NTHREADS) {
        const int r  = i >> 5;          // /32
        const int c4 = i & 31;          // float4 index within row
        const int yi = y0 - 1 + r;      // input row
        float4 v;
        if (yi >= 0 && yi < H_IN) {
            v = __ldg((const float4*)(xp + (size_t)yi * W_IN) + c4);
        } else {
            v = make_float4(0.f, 0.f, 0.f, 0.f);
        }
        float* dst = &sin_t[r][1 + c4 * 4];
        dst[0] = v.x; dst[1] = v.y; dst[2] = v.z; dst[3] = v.w;
    }
    // zero halo columns (input col -1 -> idx 0; cols 128,129 -> idx 129,130; pad 131)
    if (tid < NROWS) {
        sin_t[tid][0]   = 0.f;
        sin_t[tid][129] = 0.f;
        sin_t[tid][130] = 0.f;
        sin_t[tid][131] = 0.f;
    }
    __syncthreads();

    // ---- horizontal pass: h[r][xo] over input cols xo-1..xo+2 -> smem idx xo..xo+3 ----
    // compute 128 per row (xo=127 unused later but harmless; reads idx up to 130, zeroed)
    #pragma unroll
    for (int i = tid; i < NROWS * W_IN; i += NTHREADS) {
        const int r  = i >> 7;          // /128
        const int xo = i & 127;
        const float a = sin_t[r][xo];
        const float b = sin_t[r][xo + 1];
        const float c = sin_t[r][xo + 2];
        const float d = sin_t[r][xo + 3];
        sh_t[r][xo] = a + 3.0f * (b + c) + d;
    }
    __syncthreads();

    // ---- vertical pass + store ----
    float* op = out + (size_t)plane * (H_OUT * W_OUT);
    const int outRows = min(ROWS, H_OUT - y0);  // 32 or 31 for last tile
    #pragma unroll
    for (int i = tid; i < outRows * W_IN; i += NTHREADS) {
        const int r  = i >> 7;
        const int xo = i & 127;
        if (xo < W_OUT) {
            const float v = sh_t[r][xo] + 3.0f * (sh_t[r + 1][xo] + sh_t[r + 2][xo])
                          + sh_t[r + 3][xo];
            op[(size_t)(y0 + r) * W_OUT + xo] = v * (1.0f / 64.0f);
        }
    }
}

extern "C" void kernel_launch(void* const* d_in, const int* in_sizes, int n_in,
                              void* d_out, int out_size) {
    const float* x = (const float*)d_in[0];
    float* out = (float*)d_out;
    dim3 grid((H_OUT + ROWS - 1) / ROWS, 16 * 256);  // (4, 4096)
    fir4x4_kernel<<<grid, NTHREADS>>>(x, out);
}

// round 5
// speedup vs baseline: 1.2360x; 1.2360x over previous
#include <cuda_runtime.h>

// Depthwise separable FIR [1,3,3,1]x[1,3,3,1]/64, pad 1, 
// in: [16,256,128,128] f32 -> out: [16,256,127,127] f32
//
// Warp-per-row design: W=128 = 32 lanes x float4. Each warp streams a
// 32-output-row band of one plane. Horizontal pass via register shuffles
// (warp edges == zero padding), vertical pass via a 4-deep register ring.
// No shared memory, no __syncthreads.

#define H_IN   128
#define W_IN   128
#define H_OUT  127
#define W_OUT  127
#define BAND   32
#define NTHREADS 128   // 4 warps = 4 bands = one full plane per block

__global__ __launch_bounds__(NTHREADS)
void fir4x4_warp_kernel(const float* __restrict__ x, float* __restrict__ out) {
    const int lane  = threadIdx.x & 31;
    const int wid   = threadIdx.x >> 5;
    const int plane = blockIdx.x;                  // 0..4095
    const int y0    = wid * BAND;                  // band start (0,32,64,96)

    const float* xp = x   + (size_t)plane * (H_IN  * W_IN);
    float*       op = out + (size_t)plane * (H_OUT * W_OUT);

    float4 h0, h1, h2, h3;                         // ring of horizontal results
    h0 = h1 = h2 = h3 = make_float4(0.f, 0.f, 0.f, 0.f);

    const unsigned FULL = 0xffffffffu;

    #pragma unroll 4
    for (int i = 0; i < 36; ++i) {
        const int y = y0 - 1 + i;                  // input row
        float4 h;
        const bool live = (y >= 0) && (y < H_IN) && (i < 35);
        if (live) {
            const float4 v = __ldg((const float4*)(xp + (size_t)y * W_IN) + lane);
            // halo exchange within warp; warp edges are the zero padding
            float lw = __shfl_up_sync(FULL, v.w, 1);
            float r1 = __shfl_down_sync(FULL, v.x, 1);
            float r2 = __shfl_down_sync(FULL, v.y, 1);
            if (lane == 0)  lw = 0.f;
            if (lane == 31) { r1 = 0.f; r2 = 0.f; }
            // horizontal: h[xo] = x[xo-1] + 3*(x[xo]+x[xo+1]) + x[xo+2]
            h.x = lw  + 3.f * (v.x + v.y) + v.z;
            h.y = v.x + 3.f * (v.y + v.z) + v.w;
            h.z = v.y + 3.f * (v.z + v.w) + r1;
            h.w = v.z + 3.f * (v.w + r1)  + r2;
        } else {
            h = make_float4(0.f, 0.f, 0.f, 0.f);
        }
        // rotate ring (unroll-4 makes these register renames)
        h0 = h1; h1 = h2; h2 = h3; h3 = h;

        if (i >= 3) {
            const int yo = y - 2;                  // output row
            if (yo <= y0 + BAND - 1 && yo < H_OUT) {
                // vertical: out = (h[yo-1] + 3*(h[yo]+h[yo+1]) + h[yo+2]) / 64
                float4 o;
                o.x = (h0.x + 3.f * (h1.x + h2.x) + h3.x) * (1.f / 64.f);
                o.y = (h0.y + 3.f * (h1.y + h2.y) + h3.y) * (1.f / 64.f);
                o.z = (h0.z + 3.f * (h1.z + h2.z) + h3.z) * (1.f / 64.f);
                o.w = (h0.w + 3.f * (h1.w + h2.w) + h3.w) * (1.f / 64.f);
                // output row stride 127 is not 16B-aligned -> scalar stores
                float* orow = op + (size_t)yo * W_OUT + lane * 4;
                orow[0] = o.x;
                orow[1] = o.y;
                orow[2] = o.z;
                if (lane < 31) orow[3] = o.w;      // col 127 doesn't exist
            }
        }
    }
}

extern "C" void kernel_launch(void* const* d_in, const int* in_sizes, int n_in,
                              void* d_out, int out_size) {
    const float* x = (const float*)d_in[0];
    float* out = (float*)d_out;
    fir4x4_warp_kernel<<<16 * 256, NTHREADS>>>(x, out);
}

// round 6
// speedup vs baseline: 1.2371x; 1.0009x over previous
#include <cuda_runtime.h>

// Depthwise separable FIR [1,3,3,1]x[1,3,3,1]/64, pad 1,
// in: [16,256,128,128] f32 -> out: [16,256,127,127] f32
//
// Warp-per-row-band: W=128 = 32 lanes x float4. Horizontal pass via register
// shuffles (warp edges == zero padding). Vertical pass via 3 running
// accumulators (streaming [1,3,3,1]). Loads are UNCONDITIONAL (row index
// clamped, result masked) so the compiler batches them across the unroll
// body for high MLP. No shared memory, no syncthreads.

#define H_IN   128
#define W_IN   128
#define H_OUT  127
#define W_OUT  127
#define NTHREADS 128   // 4 warps = 4 x 32-row bands = one plane per block

__global__ __launch_bounds__(NTHREADS, 12)
void fir4x4_warp2_kernel(const float* __restrict__ x, float* __restrict__ out) {
    const int lane  = threadIdx.x & 31;
    const int wid   = threadIdx.x >> 5;
    const int plane = blockIdx.x;                  // 0..4095
    const int y0    = wid * 32;                    // band start (0,32,64,96)

    const float* xp = x   + (size_t)plane * (H_IN  * W_IN) + lane * 4;
    float*       op = out + (size_t)plane * (H_OUT * W_OUT) + lane * 4;

    // running vertical accumulators:
    //   a0 = h[j-3] + 3h[j-2] + 3h[j-1]   (completed by +h[j])
    //   a1 = h[j-2] + 3h[j-1]
    //   a2 = h[j-1]
    float4 a0 = make_float4(0.f, 0.f, 0.f, 0.f);
    float4 a1 = a0, a2 = a0;

    const unsigned FULL = 0xffffffffu;

    #pragma unroll 7
    for (int i = 0; i < 35; ++i) {
        const int y  = y0 - 1 + i;                 // h-row index
        const int yc = y < 0 ? 0 : (y > H_IN - 1 ? H_IN - 1 : y);
        // unconditional, clamped load -> compiler can hoist/batch freely
        const float4 v = *(const float4*)(xp + (size_t)yc * W_IN);

        // horizontal halo via shuffles; warp edges are the zero padding
        float lw = __shfl_up_sync(FULL, v.w, 1);
        float r1 = __shfl_down_sync(FULL, v.x, 1);
        float r2 = __shfl_down_sync(FULL, v.y, 1);
        if (lane == 0)  lw = 0.f;
        if (lane == 31) { r1 = 0.f; r2 = 0.f; }

        // h[xo] = x[xo-1] + 3*(x[xo]+x[xo+1]) + x[xo+2]
        float4 h;
        h.x = lw  + 3.f * (v.x + v.y) + v.z;
        h.y = v.x + 3.f * (v.y + v.z) + v.w;
        h.z = v.y + 3.f * (v.z + v.w) + r1;
        h.w = v.z + 3.f * (v.w + r1)  + r2;
        if ((unsigned)y >= (unsigned)H_IN) {       // rows -1, 128, 129 -> zero
            h.x = 0.f; h.y = 0.f; h.z = 0.f; h.w = 0.f;
        }

        if (i >= 3) {
            const int yo = y - 2;                  // output row (y0 .. y0+31)
            if (yo < H_OUT) {
                float* p = op + (size_t)yo * W_OUT;
                p[0] = (a0.x + h.x) * (1.f / 64.f);
                p[1] = (a0.y + h.y) * (1.f / 64.f);
                p[2] = (a0.z + h.z) * (1.f / 64.f);
                if (lane < 31) p[3] = (a0.w + h.w) * (1.f / 64.f);
            }
        }

        // advance accumulators
        float4 t;
        t.x = 3.f * h.x; t.y = 3.f * h.y; t.z = 3.f * h.z; t.w = 3.f * h.w;
        a0.x = a1.x + t.x; a0.y = a1.y + t.y; a0.z = a1.z + t.z; a0.w = a1.w + t.w;
        a1.x = a2.x + t.x; a1.y = a2.y + t.y; a1.z = a2.z + t.z; a1.w = a2.w + t.w;
        a2 = h;
    }
}

extern "C" void kernel_launch(void* const* d_in, const int* in_sizes, int n_in,
                              void* d_out, int out_size) {
    const float* x = (const float*)d_in[0];
    float* out = (float*)d_out;
    fir4x4_warp2_kernel<<<16 * 256, NTHREADS>>>(x, out);
}

// round 7
// speedup vs baseline: 1.2440x; 1.0055x over previous
#include <cuda_runtime.h>

// Depthwise separable FIR [1,3,3,1]x[1,3,3,1]/64, pad 1,
// in: [16,256,128,128] f32 -> out: [16,256,127,127] f32
//
// One warp streams one FULL plane (128 rows): zero vertical read
// amplification. W=128 = 32 lanes x float4; horizontal halo via register
// shuffles (warp edges == zero padding). Vertical pass via 3 running
// accumulators. Depth-2 explicit load pipeline; streaming cache hints.
// Exact single wave: 1024 blocks x 4 warps = 4096 warps = 4096 planes.

#define H_IN   128
#define W_IN   128
#define H_OUT  127
#define W_OUT  127
#define NTHREADS 128   // 4 warps = 4 planes per block

__device__ __forceinline__ float4 ldcs4(const float* p) {
    return __ldcs((const float4*)p);
}

__global__ __launch_bounds__(NTHREADS)
void fir4x4_plane_kernel(const float* __restrict__ x, float* __restrict__ out) {
    const int lane  = threadIdx.x & 31;
    const int wid   = threadIdx.x >> 5;
    const int plane = blockIdx.x * 4 + wid;        // 0..4095

    const float* xp = x   + (size_t)plane * (H_IN  * W_IN)  + lane * 4;
    float*       op = out + (size_t)plane * (H_OUT * W_OUT) + lane * 4;

    // vertical running accumulators over horizontal results h[]:
    //   a0 = h[j-3] + 3h[j-2] + 3h[j-1]  (completed by +h[j])
    float4 a0 = make_float4(0.f, 0.f, 0.f, 0.f);
    float4 a1 = a0, a2 = a0;

    const unsigned FULL = 0xffffffffu;

    // pipeline: v_cur holds row for h-row y = i-1 (clamped), prefetched.
    float4 v_cur = ldcs4(xp);                      // y=-1 -> clamped row 0 (masked later)

    #pragma unroll 5
    for (int i = 0; i < 130; ++i) {
        const int y = i - 1;                       // h-row index, -1..128
        // prefetch next row (y+1 clamped to [0,127])
        const int ycn = (i < H_IN) ? i : (H_IN - 1);
        const float4 v_nxt = ldcs4(xp + (size_t)ycn * W_IN);

        const float4 v = v_cur;
        // horizontal halo via shuffles; warp edges are the zero padding
        float lw = __shfl_up_sync(FULL, v.w, 1);
        float r1 = __shfl_down_sync(FULL, v.x, 1);
        float r2 = __shfl_down_sync(FULL, v.y, 1);
        if (lane == 0)  lw = 0.f;
        if (lane == 31) { r1 = 0.f; r2 = 0.f; }

        // h[xo] = x[xo-1] + 3*(x[xo]+x[xo+1]) + x[xo+2]
        float4 h;
        h.x = lw  + 3.f * (v.x + v.y) + v.z;
        h.y = v.x + 3.f * (v.y + v.z) + v.w;
        h.z = v.y + 3.f * (v.z + v.w) + r1;
        h.w = v.z + 3.f * (v.w + r1)  + r2;
        if ((unsigned)y >= (unsigned)H_IN) {       // rows -1 and 128 -> zero
            h.x = 0.f; h.y = 0.f; h.z = 0.f; h.w = 0.f;
        }

        if (i >= 3) {
            const int yo = y - 2;                  // output row 0..126
            float* p = op + (size_t)yo * W_OUT;
            __stcs(p + 0, (a0.x + h.x) * (1.f / 64.f));
            __stcs(p + 1, (a0.y + h.y) * (1.f / 64.f));
            __stcs(p + 2, (a0.z + h.z) * (1.f / 64.f));
            if (lane < 31)
                __stcs(p + 3, (a0.w + h.w) * (1.f / 64.f));   // col 127 doesn't exist
        }

        // advance accumulators
        const float hx3 = 3.f * h.x, hy3 = 3.f * h.y, hz3 = 3.f * h.z, hw3 = 3.f * h.w;
        a0.x = a1.x + hx3; a0.y = a1.y + hy3; a0.z = a1.z + hz3; a0.w = a1.w + hw3;
        a1.x = a2.x + hx3; a1.y = a2.y + hy3; a1.z = a2.z + hz3; a1.w = a2.w + hw3;
        a2 = h;

        v_cur = v_nxt;
    }
}

extern "C" void kernel_launch(void* const* d_in, const int* in_sizes, int n_in,
                              void* d_out, int out_size) {
    const float* x = (const float*)d_in[0];
    float* out = (float*)d_out;
    fir4x4_plane_kernel<<<1024, NTHREADS>>>(x, out);
}

// round 10
// speedup vs baseline: 1.4001x; 1.1255x over previous
#include <cuda_runtime.h>

// Depthwise separable FIR [1,3,3,1]x[1,3,3,1]/64, pad 1,
// in: [16,256,128,128] f32 -> out: [16,256,127,127] f32
//
// Warp = 32-output-row band of one plane. Horizontal pass via register
// shuffles (warp edges == zero padding), vertical pass via running
// accumulators. Output staged per-warp in smem in 8-row chunks placed at
// the chunk's global 16B phase, then flushed as dense aligned STG.128
// (full 32B sectors -> no ECC read-modify-write at DRAM).

#define H_IN   128
#define W_IN   128
#define H_OUT  127
#define W_OUT  127
#define NTHREADS 128          // 4 warps = 4 bands = one plane per block
#define CHUNK  8              // output rows staged per flush
#define BUFSZ  1032           // pad0(<=3) + 8*127 = 1019 -> round up

__global__ __launch_bounds__(NTHREADS)
void fir4x4_stg128_kernel(const float* __restrict__ x, float* __restrict__ out) {
    __shared__ float buf[4][BUFSZ];

    const int lane  = threadIdx.x & 31;
    const int wid   = threadIdx.x >> 5;
    const int plane = blockIdx.x;                  // 0..4095
    const int y0    = wid * 32;                    // band start
    const int nOut  = min(32, H_OUT - y0);         // 32 or 31

    const float* xp = x + (size_t)plane * (H_IN * W_IN) + lane * 4;
    float* b = buf[wid];

    float4 a0 = make_float4(0.f, 0.f, 0.f, 0.f);   // running vertical accumulators
    float4 a1 = a0, a2 = a0;
    const unsigned FULL = 0xffffffffu;

    // ---- prologue: h-rows y0-1 .. y0+1 ----
    #pragma unroll
    for (int pj = 0; pj < 3; ++pj) {
        const int j  = y0 - 1 + pj;
        const int jc = j < 0 ? 0 : (j > H_IN - 1 ? H_IN - 1 : j);
        const float4 v = __ldg((const float4*)(xp + (size_t)jc * W_IN));
        float lw = __shfl_up_sync(FULL, v.w, 1);
        float r1 = __shfl_down_sync(FULL, v.x, 1);
        float r2 = __shfl_down_sync(FULL, v.y, 1);
        if (lane == 0)  lw = 0.f;
        if (lane == 31) { r1 = 0.f; r2 = 0.f; }
        float4 h;
        h.x = lw  + 3.f * (v.x + v.y) + v.z;
        h.y = v.x + 3.f * (v.y + v.z) + v.w;
        h.z = v.y + 3.f * (v.z + v.w) + r1;
        h.w = v.z + 3.f * (v.w + r1)  + r2;
        if ((unsigned)j >= (unsigned)H_IN) { h.x = h.y = h.z = h.w = 0.f; }
        const float tx = 3.f * h.x, ty = 3.f * h.y, tz = 3.f * h.z, tw = 3.f * h.w;
        a0.x = a1.x + tx; a0.y = a1.y + ty; a0.z = a1.z + tz; a0.w = a1.w + tw;
        a1.x = a2.x + tx; a1.y = a2.y + ty; a1.z = a2.z + tz; a1.w = a2.w + tw;
        a2 = h;
    }

    // ---- main: 4 chunks of up to 8 output rows ----
    int yo = y0;
    #pragma unroll
    for (int c = 0; c < 4; ++c) {
        const int rows = min(CHUNK, y0 + nOut - yo);
        if (rows <= 0) break;
        const int chunkBase = plane * (H_OUT * W_OUT) + yo * W_OUT;  // float offset
        const int pad0 = chunkBase & 3;            // phase vs 16B alignment

        #pragma unroll
        for (int r = 0; r < CHUNK; ++r) {
            if (r >= rows) break;
            // h-row yo+2
            const int j  = yo + 2;
            const int jc = j > H_IN - 1 ? H_IN - 1 : j;
            const float4 v = __ldg((const float4*)(xp + (size_t)jc * W_IN));
            float lw = __shfl_up_sync(FULL, v.w, 1);
            float r1 = __shfl_down_sync(FULL, v.x, 1);
            float r2 = __shfl_down_sync(FULL, v.y, 1);
            if (lane == 0)  lw = 0.f;
            if (lane == 31) { r1 = 0.f; r2 = 0.f; }
            float4 h;
            h.x = lw  + 3.f * (v.x + v.y) + v.z;
            h.y = v.x + 3.f * (v.y + v.z) + v.w;
            h.z = v.y + 3.f * (v.z + v.w) + r1;
            h.w = v.z + 3.f * (v.w + r1)  + r2;
            if (j >= H_IN) { h.x = h.y = h.z = h.w = 0.f; }

            // output row yo -> smem at global 16B phase
            const int s = pad0 + r * W_OUT + lane * 4;
            b[s]     = (a0.x + h.x) * (1.f / 64.f);
            b[s + 1] = (a0.y + h.y) * (1.f / 64.f);
            b[s + 2] = (a0.z + h.z) * (1.f / 64.f);
            if (lane < 31)
                b[s + 3] = (a0.w + h.w) * (1.f / 64.f);

            // advance accumulators
            const float tx = 3.f * h.x, ty = 3.f * h.y, tz = 3.f * h.z, tw = 3.f * h.w;
            a0.x = a1.x + tx; a0.y = a1.y + ty; a0.z = a1.z + tz; a0.w = a1.w + tw;
            a1.x = a2.x + tx; a1.y = a2.y + ty; a1.z = a2.z + tz; a1.w = a2.w + tw;
            a2 = h;
            ++yo;
        }
        __syncwarp();

        // ---- flush chunk: dense aligned STG.128 over linear output ----
        const int end = pad0 + rows * W_OUT;       // valid smem slots [pad0, end)
        float* g = out + (chunkBase - pad0);       // 16B-aligned global base
        if (lane >= pad0 && lane < 4)              // head scalars (slots pad0..3)
            g[lane] = b[lane];
        const int end4 = end >> 2;
        for (int v4 = 1 + lane; v4 < end4; v4 += 32)
            *(float4*)(g + 4 * v4) = *(const float4*)(b + 4 * v4);
        const int tail = end & 3;                  // tail scalars
        if (lane < tail)
            g[(end4 << 2) + lane] = b[(end4 << 2) + lane];
        __syncwarp();
    }
}

extern "C" void kernel_launch(void* const* d_in, const int* in_sizes, int n_in,
                              void* d_out, int out_size) {
    const float* x = (const float*)d_in[0];
    float* out = (float*)d_out;
    fir4x4_stg128_kernel<<<16 * 256, NTHREADS>>>(x, out);
}